// round 4
// baseline (speedup 1.0000x reference)
#include <cuda_runtime.h>
#include <cstdint>
#include <cstddef>

// Problem constants (fixed by the reference)
#define NMAX 50000
#define EMAX 800000
#define HD   128
#define HD2  256
#define NGRAPH 64
#define NCLS 10
#define NLAYER 4
#define BN_EPS_C 1e-5f
#define STATS_BLOCKS 128

// ---------------- scratch (device globals: no allocation allowed) ----------------
__device__ float g_hA[NMAX * HD];
__device__ float g_hB[NMAX * HD];
__device__ float g_agg[NMAX * HD];
__device__ float g_t[NMAX * HD2];
__device__ float g_z[NMAX * HD];
__device__ float g_zres[NMAX * HD];
__device__ float g_psum[STATS_BLOCKS * HD];
__device__ float g_psq[STATS_BLOCKS * HD];
__device__ float g_scale[HD];
__device__ float g_shift[HD];
__device__ float g_hg[NGRAPH * HD];
__device__ float g_cnt[NGRAPH];

// ---------------- utility: zero fill (float4 granularity) ----------------
__global__ void fill_zero_kernel(float* __restrict__ p, int n4) {
    int i = blockIdx.x * blockDim.x + threadIdx.x;
    if (i < n4) reinterpret_cast<float4*>(p)[i] = make_float4(0.f, 0.f, 0.f, 0.f);
}

// ---------------- input projection: h = relu([x||pe] @ W_in + b_in) ----------------
// W_in: [80,128] row-major. Block: 128 threads, 16 rows per block.
__global__ void input_proj_kernel(const float* __restrict__ x, const float* __restrict__ pe,
                                  const float* __restrict__ W, const float* __restrict__ b,
                                  float* __restrict__ h, int M) {
    __shared__ float Ws[80 * 128];     // 40 KB
    __shared__ float rows[16][80];     // 5 KB
    for (int i = threadIdx.x; i < 80 * 128; i += 128) Ws[i] = W[i];
    int r0 = blockIdx.x * 16;
    for (int i = threadIdx.x; i < 16 * 80; i += 128) {
        int r = i / 80, c = i % 80;
        float v = 0.f;
        if (r0 + r < M)
            v = (c < 64) ? x[(size_t)(r0 + r) * 64 + c] : pe[(size_t)(r0 + r) * 16 + (c - 64)];
        rows[r][c] = v;
    }
    __syncthreads();
    int col = threadIdx.x;
    float bc = b[col];
    for (int r = 0; r < 16; r++) {
        if (r0 + r >= M) break;
        float acc = bc;
#pragma unroll 16
        for (int k = 0; k < 80; k++) acc = fmaf(rows[r][k], Ws[k * 128 + col], acc);
        h[(size_t)(r0 + r) * 128 + col] = fmaxf(acc, 0.f);
    }
}

// ---------------- edge message + aggregate ----------------
// One warp per edge (grid-stride). Each lane owns 4 output columns; the 16x4
// weight slice is held in registers (no LDS in the hot loop).
// msg = relu(h[src] + edge_attr @ We + be); atomicAdd(float4) into agg[dst].
__global__ __launch_bounds__(256)
void edge_agg_kernel(const float* __restrict__ h, const int* __restrict__ ei,
                     const float* __restrict__ ea, const float* __restrict__ We,
                     const float* __restrict__ be, float* __restrict__ agg, int E) {
    int lane = threadIdx.x & 31;
    int warp = blockIdx.x * (blockDim.x >> 5) + (threadIdx.x >> 5);
    int nwarp = gridDim.x * (blockDim.x >> 5);

    float4 w[16];
#pragma unroll
    for (int k = 0; k < 16; k++)
        w[k] = *reinterpret_cast<const float4*>(We + k * 128 + lane * 4);
    float4 b4 = *reinterpret_cast<const float4*>(be + lane * 4);

    for (int e = warp; e < E; e += nwarp) {
        int src = __ldg(ei + e);
        int dst = __ldg(ei + E + e);
        const float4* eap = reinterpret_cast<const float4*>(ea + (size_t)e * 16);
        float4 a0 = eap[0], a1 = eap[1], a2 = eap[2], a3 = eap[3];
        float av[16] = {a0.x, a0.y, a0.z, a0.w, a1.x, a1.y, a1.z, a1.w,
                        a2.x, a2.y, a2.z, a2.w, a3.x, a3.y, a3.z, a3.w};
        float4 acc = b4;
#pragma unroll
        for (int k = 0; k < 16; k++) {
            acc.x = fmaf(av[k], w[k].x, acc.x);
            acc.y = fmaf(av[k], w[k].y, acc.y);
            acc.z = fmaf(av[k], w[k].z, acc.z);
            acc.w = fmaf(av[k], w[k].w, acc.w);
        }
        float4 hv = *reinterpret_cast<const float4*>(h + (size_t)src * 128 + lane * 4);
        float4 m;
        m.x = fmaxf(hv.x + acc.x, 0.f);
        m.y = fmaxf(hv.y + acc.y, 0.f);
        m.z = fmaxf(hv.z + acc.z, 0.f);
        m.w = fmaxf(hv.w + acc.w, 0.f);
        atomicAdd(reinterpret_cast<float4*>(agg + (size_t)dst * 128 + lane * 4), m);
    }
}

// ---------------- SGEMM: C[M,NC] = epi(A'[M,K] @ B[K,NC] + bias) ----------------
// A' = FUSE_A ? (1+eps)*A + A2 : A.  Epilogue: RELU and/or + resid.
// 128x128x8 tiling, 256 threads, 8x8 microtile.
template <int K, int NC, bool FUSE_A, bool RELU, bool RESID>
__global__ __launch_bounds__(256)
void gemm_kernel(const float* __restrict__ A, const float* __restrict__ A2,
                 const float* __restrict__ epsp, const float* __restrict__ B,
                 const float* __restrict__ bias, const float* __restrict__ resid,
                 float* __restrict__ C, int M) {
    constexpr int BM = 128, BN = 128, BK = 8;
    __shared__ float As[BK][BM];
    __shared__ float Bs[BK][BN];
    int tid = threadIdx.x;
    int bm = blockIdx.y * BM;
    int bn = blockIdx.x * BN;
    int tx = tid & 15, ty = tid >> 4;
    float alpha = 1.0f;
    if (FUSE_A) alpha = 1.0f + __ldg(epsp);
    int arow = tid >> 1;       // 0..127
    int akc = (tid & 1) * 4;   // 0 or 4
    int brow = tid >> 5;       // 0..7
    int bcol = (tid & 31) * 4; // 0..124

    float acc[8][8];
#pragma unroll
    for (int i = 0; i < 8; i++)
#pragma unroll
        for (int j = 0; j < 8; j++) acc[i][j] = 0.f;

    for (int k0 = 0; k0 < K; k0 += BK) {
        float4 av = make_float4(0.f, 0.f, 0.f, 0.f);
        int gr = bm + arow;
        if (gr < M) {
            av = *reinterpret_cast<const float4*>(A + (size_t)gr * K + k0 + akc);
            if (FUSE_A) {
                float4 gv = *reinterpret_cast<const float4*>(A2 + (size_t)gr * K + k0 + akc);
                av.x = fmaf(alpha, av.x, gv.x);
                av.y = fmaf(alpha, av.y, gv.y);
                av.z = fmaf(alpha, av.z, gv.z);
                av.w = fmaf(alpha, av.w, gv.w);
            }
        }
        As[akc + 0][arow] = av.x;
        As[akc + 1][arow] = av.y;
        As[akc + 2][arow] = av.z;
        As[akc + 3][arow] = av.w;
        *reinterpret_cast<float4*>(&Bs[brow][bcol]) =
            *reinterpret_cast<const float4*>(B + (size_t)(k0 + brow) * NC + bn + bcol);
        __syncthreads();
#pragma unroll
        for (int kk = 0; kk < BK; kk++) {
            float ar[8], br[8];
            *reinterpret_cast<float4*>(ar) = *reinterpret_cast<float4*>(&As[kk][ty * 8]);
            *reinterpret_cast<float4*>(ar + 4) = *reinterpret_cast<float4*>(&As[kk][ty * 8 + 4]);
            *reinterpret_cast<float4*>(br) = *reinterpret_cast<float4*>(&Bs[kk][tx * 8]);
            *reinterpret_cast<float4*>(br + 4) = *reinterpret_cast<float4*>(&Bs[kk][tx * 8 + 4]);
#pragma unroll
            for (int i = 0; i < 8; i++)
#pragma unroll
                for (int j = 0; j < 8; j++) acc[i][j] = fmaf(ar[i], br[j], acc[i][j]);
        }
        __syncthreads();
    }

    int c0 = bn + tx * 8;
    float bb[8];
    *reinterpret_cast<float4*>(bb) = *reinterpret_cast<const float4*>(bias + c0);
    *reinterpret_cast<float4*>(bb + 4) = *reinterpret_cast<const float4*>(bias + c0 + 4);
#pragma unroll
    for (int i = 0; i < 8; i++) {
        int r = bm + ty * 8 + i;
        if (r >= M) break;
        float v[8];
#pragma unroll
        for (int j = 0; j < 8; j++) {
            v[j] = acc[i][j] + bb[j];
            if (RELU) v[j] = fmaxf(v[j], 0.f);
        }
        if (RESID) {
            float4 r0 = *reinterpret_cast<const float4*>(resid + (size_t)r * NC + c0);
            float4 r1 = *reinterpret_cast<const float4*>(resid + (size_t)r * NC + c0 + 4);
            v[0] += r0.x; v[1] += r0.y; v[2] += r0.z; v[3] += r0.w;
            v[4] += r1.x; v[5] += r1.y; v[6] += r1.z; v[7] += r1.w;
        }
        *reinterpret_cast<float4*>(C + (size_t)r * NC + c0) = *reinterpret_cast<float4*>(v);
        *reinterpret_cast<float4*>(C + (size_t)r * NC + c0 + 4) = *reinterpret_cast<float4*>(v + 4);
    }
}

// ---------------- batch norm (train-style batch stats) ----------------
__global__ void bn_stats_kernel(const float* __restrict__ X, int M) {
    int col = threadIdx.x & 127;
    int half = threadIdx.x >> 7;
    float s = 0.f, q = 0.f;
    for (int r = blockIdx.x * 2 + half; r < M; r += gridDim.x * 2) {
        float v = X[(size_t)r * 128 + col];
        s += v;
        q = fmaf(v, v, q);
    }
    __shared__ float ss[256], qq[256];
    ss[threadIdx.x] = s;
    qq[threadIdx.x] = q;
    __syncthreads();
    if (half == 0) {
        g_psum[blockIdx.x * 128 + col] = ss[col] + ss[col + 128];
        g_psq[blockIdx.x * 128 + col] = qq[col] + qq[col + 128];
    }
}

__global__ void bn_finalize_kernel(const float* __restrict__ g, const float* __restrict__ b,
                                   int M, int nblk) {
    int col = threadIdx.x; // 128 threads
    float s = 0.f, q = 0.f;
    for (int i = 0; i < nblk; i++) {
        s += g_psum[i * 128 + col];
        q += g_psq[i * 128 + col];
    }
    float mean = s / (float)M;
    float var = q / (float)M - mean * mean;
    float sc = g[col] * rsqrtf(var + BN_EPS_C);
    g_scale[col] = sc;
    g_shift[col] = b[col] - mean * sc;
}

// zres = relu(bn(z)) + h
__global__ void bn1_apply_kernel(const float* __restrict__ z, const float* __restrict__ h,
                                 float* __restrict__ zres, int M) {
    int i = blockIdx.x * blockDim.x + threadIdx.x;
    if (i >= M * 32) return;
    int c = i & 31;
    float4 sc = *reinterpret_cast<const float4*>(g_scale + c * 4);
    float4 sh = *reinterpret_cast<const float4*>(g_shift + c * 4);
    float4 zv = reinterpret_cast<const float4*>(z)[i];
    float4 hv = reinterpret_cast<const float4*>(h)[i];
    float4 o;
    o.x = fmaxf(fmaf(zv.x, sc.x, sh.x), 0.f) + hv.x;
    o.y = fmaxf(fmaf(zv.y, sc.y, sh.y), 0.f) + hv.y;
    o.z = fmaxf(fmaf(zv.z, sc.z, sh.z), 0.f) + hv.z;
    o.w = fmaxf(fmaf(zv.w, sc.w, sh.w), 0.f) + hv.w;
    reinterpret_cast<float4*>(zres)[i] = o;
}

// hn = bn(s)
__global__ void bn2_apply_kernel(const float* __restrict__ s, float* __restrict__ hn, int M) {
    int i = blockIdx.x * blockDim.x + threadIdx.x;
    if (i >= M * 32) return;
    int c = i & 31;
    float4 sc = *reinterpret_cast<const float4*>(g_scale + c * 4);
    float4 sh = *reinterpret_cast<const float4*>(g_shift + c * 4);
    float4 sv = reinterpret_cast<const float4*>(s)[i];
    float4 o;
    o.x = fmaf(sv.x, sc.x, sh.x);
    o.y = fmaf(sv.y, sc.y, sh.y);
    o.z = fmaf(sv.z, sc.z, sh.z);
    o.w = fmaf(sv.w, sc.w, sh.w);
    reinterpret_cast<float4*>(hn)[i] = o;
}

// ---------------- global mean pool + readout ----------------
__global__ void pool_kernel(const float* __restrict__ h, const int* __restrict__ batch, int M) {
    int i = blockIdx.x * blockDim.x + threadIdx.x;
    if (i >= M * 32) return;
    int r = i >> 5, c = i & 31;
    int g = __ldg(batch + r);
    float4 v = reinterpret_cast<const float4*>(h)[i];
    atomicAdd(reinterpret_cast<float4*>(g_hg) + g * 32 + c, v);
    if (c == 0) atomicAdd(&g_cnt[g], 1.0f);
}

__global__ void pool_norm_kernel() {
    int i = blockIdx.x * blockDim.x + threadIdx.x;
    if (i < NGRAPH * HD) g_hg[i] /= fmaxf(g_cnt[i >> 7], 1.0f);
}

__global__ void readout_kernel(const float* __restrict__ W1, const float* __restrict__ b1,
                               const float* __restrict__ W2, const float* __restrict__ b2,
                               float* __restrict__ out) {
    __shared__ float u[NGRAPH * HD]; // 32 KB
    int tid = threadIdx.x;           // 256
    for (int i = tid; i < NGRAPH * HD; i += 256) {
        int g = i >> 7, c = i & 127;
        float acc = b1[c];
#pragma unroll 8
        for (int k = 0; k < 128; k++) acc = fmaf(g_hg[g * 128 + k], W1[k * 128 + c], acc);
        u[i] = fmaxf(acc, 0.f);
    }
    __syncthreads();
    for (int i = tid; i < NGRAPH * NCLS; i += 256) {
        int g = i / NCLS, c = i % NCLS;
        float acc = b2[c];
#pragma unroll 8
        for (int k = 0; k < 128; k++) acc = fmaf(u[g * 128 + k], W2[k * NCLS + c], acc);
        out[i] = acc;
    }
}

// ---------------- launch ----------------
extern "C" void kernel_launch(void* const* d_in, const int* in_sizes, int n_in,
                              void* d_out, int out_size) {
    const float* x = (const float*)d_in[0];
    const float* pe = (const float*)d_in[1];
    const int* ei = (const int*)d_in[2];
    const float* ea = (const float*)d_in[3];
    const int* batch = (const int*)d_in[4];
    const float* W_in = (const float*)d_in[5];
    const float* b_in = (const float*)d_in[6];
    const float* We = (const float*)d_in[7];
    const float* bee = (const float*)d_in[8];
    const float* eps = (const float*)d_in[9];
    const float* W1g = (const float*)d_in[10];
    const float* b1g = (const float*)d_in[11];
    const float* W2g = (const float*)d_in[12];
    const float* b2g = (const float*)d_in[13];
    const float* bn1g = (const float*)d_in[14];
    const float* bn1b = (const float*)d_in[15];
    const float* W1f = (const float*)d_in[16];
    const float* b1f = (const float*)d_in[17];
    const float* W2f = (const float*)d_in[18];
    const float* b2f = (const float*)d_in[19];
    const float* bn2g = (const float*)d_in[20];
    const float* bn2b = (const float*)d_in[21];
    const float* Wr1 = (const float*)d_in[22];
    const float* br1 = (const float*)d_in[23];
    const float* Wr2 = (const float*)d_in[24];
    const float* br2 = (const float*)d_in[25];
    float* out = (float*)d_out;

    int M = in_sizes[0] / 64;  // N nodes
    int E = in_sizes[2] / 2;   // edges

    float *hA, *hB, *agg, *tb, *zb, *zres, *hg, *cnt;
    cudaGetSymbolAddress((void**)&hA, g_hA);
    cudaGetSymbolAddress((void**)&hB, g_hB);
    cudaGetSymbolAddress((void**)&agg, g_agg);
    cudaGetSymbolAddress((void**)&tb, g_t);
    cudaGetSymbolAddress((void**)&zb, g_z);
    cudaGetSymbolAddress((void**)&zres, g_zres);
    cudaGetSymbolAddress((void**)&hg, g_hg);
    cudaGetSymbolAddress((void**)&cnt, g_cnt);

    input_proj_kernel<<<(M + 15) / 16, 128>>>(x, pe, W_in, b_in, hA, M);

    float* cur = hA;
    float* nxt = hB;
    int n4 = M * 32;              // float4 elements in an [M,128] buffer
    int ewBlocks = 1024;          // grid-stride edge warps
    dim3 gW(2, (M + 127) / 128);  // NC=256
    dim3 gN(1, (M + 127) / 128);  // NC=128
    int eb = (n4 + 255) / 256;

    for (int l = 0; l < NLAYER; l++) {
        // GINEConv aggregate
        fill_zero_kernel<<<eb, 256>>>(agg, n4);
        edge_agg_kernel<<<ewBlocks, 256>>>(cur, ei, ea, We + l * 16 * 128, bee + l * 128, agg, E);
        // GIN MLP: t = relu(((1+eps)h + agg) @ W1 + b1); z = t @ W2 + b2
        gemm_kernel<128, 256, true, true, false><<<gW, 256>>>(
            cur, agg, eps + l, W1g + (size_t)l * 128 * 256, b1g + l * 256, nullptr, tb, M);
        gemm_kernel<256, 128, false, false, false><<<gN, 256>>>(
            tb, nullptr, nullptr, W2g + (size_t)l * 256 * 128, b2g + l * 128, nullptr, zb, M);
        // BN1 -> relu -> + h  => zres
        bn_stats_kernel<<<STATS_BLOCKS, 256>>>(zb, M);
        bn_finalize_kernel<<<1, 128>>>(bn1g + l * 128, bn1b + l * 128, M, STATS_BLOCKS);
        bn1_apply_kernel<<<eb, 256>>>(zb, cur, zres, M);
        // FFN: t = relu(zres @ W1f + b1f); s = t @ W2f + b2f + zres  => zb
        gemm_kernel<128, 256, false, true, false><<<gW, 256>>>(
            zres, nullptr, nullptr, W1f + (size_t)l * 128 * 256, b1f + l * 256, nullptr, tb, M);
        gemm_kernel<256, 128, false, false, true><<<gN, 256>>>(
            tb, nullptr, nullptr, W2f + (size_t)l * 256 * 128, b2f + l * 128, zres, zb, M);
        // BN2 => next h
        bn_stats_kernel<<<STATS_BLOCKS, 256>>>(zb, M);
        bn_finalize_kernel<<<1, 128>>>(bn2g + l * 128, bn2b + l * 128, M, STATS_BLOCKS);
        bn2_apply_kernel<<<eb, 256>>>(zb, nxt, M);
        float* tmp = cur; cur = nxt; nxt = tmp;
    }

    // Global mean pool + readout
    fill_zero_kernel<<<(NGRAPH * 32 + 255) / 256, 256>>>(hg, NGRAPH * 32);
    fill_zero_kernel<<<1, 64>>>(cnt, NGRAPH / 4);
    pool_kernel<<<eb, 256>>>(cur, batch, M);
    pool_norm_kernel<<<(NGRAPH * HD + 255) / 256, 256>>>();
    readout_kernel<<<1, 256>>>(Wr1, br1, Wr2, br2, out);
}

// round 5
// speedup vs baseline: 1.2570x; 1.2570x over previous
#include <cuda_runtime.h>
#include <cstdint>
#include <cstddef>

// Problem constants (fixed by the reference)
#define NMAX 50000
#define EMAX 800000
#define HD   128
#define HD2  256
#define NGRAPH 64
#define NCLS 10
#define NLAYER 4
#define BN_EPS_C 1e-5f

// ---------------- scratch (device globals: no allocation allowed) ----------------
__device__ float g_hA[NMAX * HD];
__device__ float g_hB[NMAX * HD];
__device__ float g_agg[NMAX * HD];
__device__ float g_t[NMAX * HD2];
__device__ float g_z[NMAX * HD];
__device__ float g_zres[NMAX * HD];
__device__ float g_psum[HD];
__device__ float g_psq[HD];
__device__ float g_scale[HD];
__device__ float g_shift[HD];
__device__ float g_hg[NGRAPH * HD];
__device__ float g_cnt[NGRAPH];

// ---------------- utility ----------------
__global__ void fill_zero_kernel(float* __restrict__ p, int n4) {
    int i = blockIdx.x * blockDim.x + threadIdx.x;
    if (i < n4) reinterpret_cast<float4*>(p)[i] = make_float4(0.f, 0.f, 0.f, 0.f);
}

__device__ __forceinline__ uint32_t f2tf(float x) {
    uint32_t r;
    asm("cvt.rna.tf32.f32 %0, %1;" : "=r"(r) : "f"(x));
    return r;
}

__device__ __forceinline__ void mma8(float* c, const uint32_t* a, const uint32_t* b) {
    asm volatile(
        "mma.sync.aligned.m16n8k8.row.col.f32.tf32.tf32.f32 "
        "{%0,%1,%2,%3}, {%4,%5,%6,%7}, {%8,%9}, {%0,%1,%2,%3};"
        : "+f"(c[0]), "+f"(c[1]), "+f"(c[2]), "+f"(c[3])
        : "r"(a[0]), "r"(a[1]), "r"(a[2]), "r"(a[3]), "r"(b[0]), "r"(b[1]));
}

// ---------------- input projection: h = relu([x||pe] @ W_in + b_in) ----------------
__global__ void input_proj_kernel(const float* __restrict__ x, const float* __restrict__ pe,
                                  const float* __restrict__ W, const float* __restrict__ b,
                                  float* __restrict__ h, int M) {
    __shared__ float Ws[80 * 128];
    __shared__ float rows[16][80];
    for (int i = threadIdx.x; i < 80 * 128; i += 128) Ws[i] = W[i];
    int r0 = blockIdx.x * 16;
    for (int i = threadIdx.x; i < 16 * 80; i += 128) {
        int r = i / 80, c = i % 80;
        float v = 0.f;
        if (r0 + r < M)
            v = (c < 64) ? x[(size_t)(r0 + r) * 64 + c] : pe[(size_t)(r0 + r) * 16 + (c - 64)];
        rows[r][c] = v;
    }
    __syncthreads();
    int col = threadIdx.x;
    float bc = b[col];
    for (int r = 0; r < 16; r++) {
        if (r0 + r >= M) break;
        float acc = bc;
#pragma unroll 16
        for (int k = 0; k < 80; k++) acc = fmaf(rows[r][k], Ws[k * 128 + col], acc);
        h[(size_t)(r0 + r) * 128 + col] = fmaxf(acc, 0.f);
    }
}

// ---------------- edge message + aggregate ----------------
__global__ __launch_bounds__(256)
void edge_agg_kernel(const float* __restrict__ h, const int* __restrict__ ei,
                     const float* __restrict__ ea, const float* __restrict__ We,
                     const float* __restrict__ be, float* __restrict__ agg, int E) {
    int lane = threadIdx.x & 31;
    int warp = blockIdx.x * (blockDim.x >> 5) + (threadIdx.x >> 5);
    int nwarp = gridDim.x * (blockDim.x >> 5);

    float4 w[16];
#pragma unroll
    for (int k = 0; k < 16; k++)
        w[k] = *reinterpret_cast<const float4*>(We + k * 128 + lane * 4);
    float4 b4 = *reinterpret_cast<const float4*>(be + lane * 4);

    for (int e = warp; e < E; e += nwarp) {
        int src = __ldg(ei + e);
        int dst = __ldg(ei + E + e);
        const float4* eap = reinterpret_cast<const float4*>(ea + (size_t)e * 16);
        float4 a0 = eap[0], a1 = eap[1], a2 = eap[2], a3 = eap[3];
        float av[16] = {a0.x, a0.y, a0.z, a0.w, a1.x, a1.y, a1.z, a1.w,
                        a2.x, a2.y, a2.z, a2.w, a3.x, a3.y, a3.z, a3.w};
        float4 acc = b4;
#pragma unroll
        for (int k = 0; k < 16; k++) {
            acc.x = fmaf(av[k], w[k].x, acc.x);
            acc.y = fmaf(av[k], w[k].y, acc.y);
            acc.z = fmaf(av[k], w[k].z, acc.z);
            acc.w = fmaf(av[k], w[k].w, acc.w);
        }
        float4 hv = *reinterpret_cast<const float4*>(h + (size_t)src * 128 + lane * 4);
        float4 m;
        m.x = fmaxf(hv.x + acc.x, 0.f);
        m.y = fmaxf(hv.y + acc.y, 0.f);
        m.z = fmaxf(hv.z + acc.z, 0.f);
        m.w = fmaxf(hv.w + acc.w, 0.f);
        atomicAdd(reinterpret_cast<float4*>(agg + (size_t)dst * 128 + lane * 4), m);
    }
}

// ---------------- 3xTF32 tensor-core GEMM ----------------
// C[M,NC] = epi(A'[M,K] @ B[K,NC] + bias)
// A' = FUSE_A ? (1+eps)*A + A2 : A.  Epilogue: RELU / +resid / BN partial stats.
// Block: 128x128 tile, 256 threads (8 warps, 2m x 4n), warp tile 64x32.
// hi/lo tf32 split done once at smem staging; 3 MMAs per tile (hh, hl, lh).
template <int K, int NC, bool FUSE_A, bool RELU, bool RESID, bool STATS>
__global__ __launch_bounds__(256)
void gemm_tc(const float* __restrict__ A, const float* __restrict__ A2,
             const float* __restrict__ epsp, const float* __restrict__ B,
             const float* __restrict__ bias, const float* __restrict__ resid,
             float* __restrict__ C, int M) {
    constexpr int BM = 128, BN = 128, BK = 16;
    __shared__ uint32_t AsH[BM][BK + 4], AsL[BM][BK + 4];   // stride 20: conflict-free
    __shared__ uint32_t BsH[BK][BN + 8], BsL[BK][BN + 8];   // stride 136: conflict-free
    int tid = threadIdx.x, lane = tid & 31, warp = tid >> 5;
    int wm = warp >> 2, wn = warp & 3;
    int bm = blockIdx.y * BM, bn = blockIdx.x * BN;
    float alpha = 1.0f;
    if (FUSE_A) alpha = 1.0f + __ldg(epsp);

    float acc[4][4][4];
#pragma unroll
    for (int i = 0; i < 4; i++)
#pragma unroll
        for (int j = 0; j < 4; j++)
#pragma unroll
            for (int q = 0; q < 4; q++) acc[i][j][q] = 0.f;

    for (int k0 = 0; k0 < K; k0 += BK) {
        // stage A tile [BM x BK] (2 float4 per thread), split hi/lo
#pragma unroll
        for (int i = 0; i < 2; i++) {
            int lin = tid + i * 256;
            int r = lin >> 2, c4 = (lin & 3) * 4;
            float4 v = make_float4(0.f, 0.f, 0.f, 0.f);
            int gr = bm + r;
            if (gr < M) {
                v = *reinterpret_cast<const float4*>(A + (size_t)gr * K + k0 + c4);
                if (FUSE_A) {
                    float4 g = *reinterpret_cast<const float4*>(A2 + (size_t)gr * K + k0 + c4);
                    v.x = fmaf(alpha, v.x, g.x);
                    v.y = fmaf(alpha, v.y, g.y);
                    v.z = fmaf(alpha, v.z, g.z);
                    v.w = fmaf(alpha, v.w, g.w);
                }
            }
            float vv[4] = {v.x, v.y, v.z, v.w};
#pragma unroll
            for (int j = 0; j < 4; j++) {
                uint32_t hbits = f2tf(vv[j]);
                float lof = vv[j] - __uint_as_float(hbits);
                AsH[r][c4 + j] = hbits;
                AsL[r][c4 + j] = f2tf(lof);
            }
        }
        // stage B tile [BK x BN]
#pragma unroll
        for (int i = 0; i < 2; i++) {
            int lin = tid + i * 256;
            int r = lin >> 5, c4 = (lin & 31) * 4;
            float4 v = *reinterpret_cast<const float4*>(B + (size_t)(k0 + r) * NC + bn + c4);
            float vv[4] = {v.x, v.y, v.z, v.w};
#pragma unroll
            for (int j = 0; j < 4; j++) {
                uint32_t hbits = f2tf(vv[j]);
                float lof = vv[j] - __uint_as_float(hbits);
                BsH[r][c4 + j] = hbits;
                BsL[r][c4 + j] = f2tf(lof);
            }
        }
        __syncthreads();
#pragma unroll
        for (int ks = 0; ks < BK; ks += 8) {
            uint32_t aH[4][4], aL[4][4], bH[4][2], bL[4][2];
            int ar = wm * 64 + (lane >> 2);
            int ac = ks + (lane & 3);
#pragma unroll
            for (int mt = 0; mt < 4; mt++) {
                int r0 = ar + mt * 16;
                aH[mt][0] = AsH[r0][ac];
                aH[mt][1] = AsH[r0 + 8][ac];
                aH[mt][2] = AsH[r0][ac + 4];
                aH[mt][3] = AsH[r0 + 8][ac + 4];
                aL[mt][0] = AsL[r0][ac];
                aL[mt][1] = AsL[r0 + 8][ac];
                aL[mt][2] = AsL[r0][ac + 4];
                aL[mt][3] = AsL[r0 + 8][ac + 4];
            }
            int br = ks + (lane & 3);
#pragma unroll
            for (int nt = 0; nt < 4; nt++) {
                int cc = wn * 32 + nt * 8 + (lane >> 2);
                bH[nt][0] = BsH[br][cc];
                bH[nt][1] = BsH[br + 4][cc];
                bL[nt][0] = BsL[br][cc];
                bL[nt][1] = BsL[br + 4][cc];
            }
#pragma unroll
            for (int mt = 0; mt < 4; mt++)
#pragma unroll
                for (int nt = 0; nt < 4; nt++) {
                    mma8(acc[mt][nt], aH[mt], bH[nt]);
                    mma8(acc[mt][nt], aH[mt], bL[nt]);
                    mma8(acc[mt][nt], aL[mt], bH[nt]);
                }
        }
        __syncthreads();
    }

    // epilogue: bias, relu, resid, store; optional BN partial stats
    float ss[8], sq[8];
#pragma unroll
    for (int j = 0; j < 8; j++) { ss[j] = 0.f; sq[j] = 0.f; }
#pragma unroll
    for (int nt = 0; nt < 4; nt++) {
        int c = bn + wn * 32 + nt * 8 + (lane & 3) * 2;
        float b0 = __ldg(bias + c), b1 = __ldg(bias + c + 1);
#pragma unroll
        for (int mt = 0; mt < 4; mt++) {
#pragma unroll
            for (int half = 0; half < 2; half++) {
                int r = bm + wm * 64 + mt * 16 + (lane >> 2) + half * 8;
                if (r < M) {
                    float v0 = acc[mt][nt][half * 2 + 0] + b0;
                    float v1 = acc[mt][nt][half * 2 + 1] + b1;
                    if (RELU) { v0 = fmaxf(v0, 0.f); v1 = fmaxf(v1, 0.f); }
                    if (RESID) {
                        float2 rv = *reinterpret_cast<const float2*>(resid + (size_t)r * NC + c);
                        v0 += rv.x;
                        v1 += rv.y;
                    }
                    *reinterpret_cast<float2*>(C + (size_t)r * NC + c) = make_float2(v0, v1);
                    if (STATS) {
                        ss[nt * 2] += v0;
                        ss[nt * 2 + 1] += v1;
                        sq[nt * 2] = fmaf(v0, v0, sq[nt * 2]);
                        sq[nt * 2 + 1] = fmaf(v1, v1, sq[nt * 2 + 1]);
                    }
                }
            }
        }
    }
    if (STATS) {
#pragma unroll
        for (int j = 0; j < 8; j++) {
#pragma unroll
            for (int o = 16; o >= 4; o >>= 1) {
                ss[j] += __shfl_xor_sync(0xFFFFFFFFu, ss[j], o);
                sq[j] += __shfl_xor_sync(0xFFFFFFFFu, sq[j], o);
            }
        }
        if ((lane >> 2) == 0) {  // lanes 0..3 hold column totals
#pragma unroll
            for (int nt = 0; nt < 4; nt++) {
                int c = wn * 32 + nt * 8 + lane * 2;  // STATS only used with NC=128, bn=0
                atomicAdd(&g_psum[c], ss[nt * 2]);
                atomicAdd(&g_psum[c + 1], ss[nt * 2 + 1]);
                atomicAdd(&g_psq[c], sq[nt * 2]);
                atomicAdd(&g_psq[c + 1], sq[nt * 2 + 1]);
            }
        }
    }
}

// ---------------- batch norm finalize (stats came from GEMM epilogue) ----------------
__global__ void bn_finalize_kernel(const float* __restrict__ g, const float* __restrict__ b,
                                   int M) {
    int col = threadIdx.x;  // 128 threads
    float s = g_psum[col], q = g_psq[col];
    g_psum[col] = 0.f;  // re-arm for the next accumulation (graph-replay deterministic)
    g_psq[col] = 0.f;
    float mean = s / (float)M;
    float var = q / (float)M - mean * mean;
    float sc = g[col] * rsqrtf(var + BN_EPS_C);
    g_scale[col] = sc;
    g_shift[col] = b[col] - mean * sc;
}

// zres = relu(bn(z)) + h
__global__ void bn1_apply_kernel(const float* __restrict__ z, const float* __restrict__ h,
                                 float* __restrict__ zres, int M) {
    int i = blockIdx.x * blockDim.x + threadIdx.x;
    if (i >= M * 32) return;
    int c = i & 31;
    float4 sc = *reinterpret_cast<const float4*>(g_scale + c * 4);
    float4 sh = *reinterpret_cast<const float4*>(g_shift + c * 4);
    float4 zv = reinterpret_cast<const float4*>(z)[i];
    float4 hv = reinterpret_cast<const float4*>(h)[i];
    float4 o;
    o.x = fmaxf(fmaf(zv.x, sc.x, sh.x), 0.f) + hv.x;
    o.y = fmaxf(fmaf(zv.y, sc.y, sh.y), 0.f) + hv.y;
    o.z = fmaxf(fmaf(zv.z, sc.z, sh.z), 0.f) + hv.z;
    o.w = fmaxf(fmaf(zv.w, sc.w, sh.w), 0.f) + hv.w;
    reinterpret_cast<float4*>(zres)[i] = o;
}

// hn = bn(s)
__global__ void bn2_apply_kernel(const float* __restrict__ s, float* __restrict__ hn, int M) {
    int i = blockIdx.x * blockDim.x + threadIdx.x;
    if (i >= M * 32) return;
    int c = i & 31;
    float4 sc = *reinterpret_cast<const float4*>(g_scale + c * 4);
    float4 sh = *reinterpret_cast<const float4*>(g_shift + c * 4);
    float4 sv = reinterpret_cast<const float4*>(s)[i];
    float4 o;
    o.x = fmaf(sv.x, sc.x, sh.x);
    o.y = fmaf(sv.y, sc.y, sh.y);
    o.z = fmaf(sv.z, sc.z, sh.z);
    o.w = fmaf(sv.w, sc.w, sh.w);
    reinterpret_cast<float4*>(hn)[i] = o;
}

// ---------------- global mean pool + readout ----------------
__global__ void pool_kernel(const float* __restrict__ h, const int* __restrict__ batch, int M) {
    int i = blockIdx.x * blockDim.x + threadIdx.x;
    if (i >= M * 32) return;
    int r = i >> 5, c = i & 31;
    int g = __ldg(batch + r);
    float4 v = reinterpret_cast<const float4*>(h)[i];
    atomicAdd(reinterpret_cast<float4*>(g_hg) + g * 32 + c, v);
    if (c == 0) atomicAdd(&g_cnt[g], 1.0f);
}

__global__ void pool_norm_kernel() {
    int i = blockIdx.x * blockDim.x + threadIdx.x;
    if (i < NGRAPH * HD) g_hg[i] /= fmaxf(g_cnt[i >> 7], 1.0f);
}

__global__ void readout_kernel(const float* __restrict__ W1, const float* __restrict__ b1,
                               const float* __restrict__ W2, const float* __restrict__ b2,
                               float* __restrict__ out) {
    __shared__ float u[NGRAPH * HD];
    int tid = threadIdx.x;  // 256
    for (int i = tid; i < NGRAPH * HD; i += 256) {
        int g = i >> 7, c = i & 127;
        float acc = b1[c];
#pragma unroll 8
        for (int k = 0; k < 128; k++) acc = fmaf(g_hg[g * 128 + k], W1[k * 128 + c], acc);
        u[i] = fmaxf(acc, 0.f);
    }
    __syncthreads();
    for (int i = tid; i < NGRAPH * NCLS; i += 256) {
        int g = i / NCLS, c = i % NCLS;
        float acc = b2[c];
#pragma unroll 8
        for (int k = 0; k < 128; k++) acc = fmaf(u[g * 128 + k], W2[k * NCLS + c], acc);
        out[i] = acc;
    }
}

// ---------------- launch ----------------
extern "C" void kernel_launch(void* const* d_in, const int* in_sizes, int n_in,
                              void* d_out, int out_size) {
    const float* x = (const float*)d_in[0];
    const float* pe = (const float*)d_in[1];
    const int* ei = (const int*)d_in[2];
    const float* ea = (const float*)d_in[3];
    const int* batch = (const int*)d_in[4];
    const float* W_in = (const float*)d_in[5];
    const float* b_in = (const float*)d_in[6];
    const float* We = (const float*)d_in[7];
    const float* bee = (const float*)d_in[8];
    const float* eps = (const float*)d_in[9];
    const float* W1g = (const float*)d_in[10];
    const float* b1g = (const float*)d_in[11];
    const float* W2g = (const float*)d_in[12];
    const float* b2g = (const float*)d_in[13];
    const float* bn1g = (const float*)d_in[14];
    const float* bn1b = (const float*)d_in[15];
    const float* W1f = (const float*)d_in[16];
    const float* b1f = (const float*)d_in[17];
    const float* W2f = (const float*)d_in[18];
    const float* b2f = (const float*)d_in[19];
    const float* bn2g = (const float*)d_in[20];
    const float* bn2b = (const float*)d_in[21];
    const float* Wr1 = (const float*)d_in[22];
    const float* br1 = (const float*)d_in[23];
    const float* Wr2 = (const float*)d_in[24];
    const float* br2 = (const float*)d_in[25];
    float* out = (float*)d_out;

    int M = in_sizes[0] / 64;  // N nodes
    int E = in_sizes[2] / 2;   // edges

    float *hA, *hB, *agg, *tb, *zb, *zres, *hg, *cnt, *psum, *psq;
    cudaGetSymbolAddress((void**)&hA, g_hA);
    cudaGetSymbolAddress((void**)&hB, g_hB);
    cudaGetSymbolAddress((void**)&agg, g_agg);
    cudaGetSymbolAddress((void**)&tb, g_t);
    cudaGetSymbolAddress((void**)&zb, g_z);
    cudaGetSymbolAddress((void**)&zres, g_zres);
    cudaGetSymbolAddress((void**)&hg, g_hg);
    cudaGetSymbolAddress((void**)&cnt, g_cnt);
    cudaGetSymbolAddress((void**)&psum, g_psum);
    cudaGetSymbolAddress((void**)&psq, g_psq);

    // re-arm BN partial-sum accumulators (deterministic across graph replays)
    fill_zero_kernel<<<1, 64>>>(psum, HD / 4);
    fill_zero_kernel<<<1, 64>>>(psq, HD / 4);

    input_proj_kernel<<<(M + 15) / 16, 128>>>(x, pe, W_in, b_in, hA, M);

    float* cur = hA;
    float* nxt = hB;
    int n4 = M * 32;              // float4 elements in an [M,128] buffer
    int ewBlocks = 2048;          // grid-stride edge warps
    dim3 gW(2, (M + 127) / 128);  // NC=256
    dim3 gN(1, (M + 127) / 128);  // NC=128
    int eb = (n4 + 255) / 256;

    for (int l = 0; l < NLAYER; l++) {
        // GINEConv aggregate
        fill_zero_kernel<<<eb, 256>>>(agg, n4);
        edge_agg_kernel<<<ewBlocks, 256>>>(cur, ei, ea, We + l * 16 * 128, bee + l * 128, agg, E);
        // GIN MLP: t = relu(((1+eps)h + agg) @ W1 + b1); z = t @ W2 + b2 (+BN1 stats)
        gemm_tc<128, 256, true, true, false, false><<<gW, 256>>>(
            cur, agg, eps + l, W1g + (size_t)l * 128 * 256, b1g + l * 256, nullptr, tb, M);
        gemm_tc<256, 128, false, false, false, true><<<gN, 256>>>(
            tb, nullptr, nullptr, W2g + (size_t)l * 256 * 128, b2g + l * 128, nullptr, zb, M);
        bn_finalize_kernel<<<1, 128>>>(bn1g + l * 128, bn1b + l * 128, M);
        bn1_apply_kernel<<<eb, 256>>>(zb, cur, zres, M);
        // FFN: t = relu(zres @ W1f + b1f); s = t @ W2f + b2f + zres (+BN2 stats)
        gemm_tc<128, 256, false, true, false, false><<<gW, 256>>>(
            zres, nullptr, nullptr, W1f + (size_t)l * 128 * 256, b1f + l * 256, nullptr, tb, M);
        gemm_tc<256, 128, false, false, true, true><<<gN, 256>>>(
            tb, nullptr, nullptr, W2f + (size_t)l * 256 * 128, b2f + l * 128, zres, zb, M);
        bn_finalize_kernel<<<1, 128>>>(bn2g + l * 128, bn2b + l * 128, M);
        bn2_apply_kernel<<<eb, 256>>>(zb, nxt, M);
        float* tmp = cur; cur = nxt; nxt = tmp;
    }

    // Global mean pool + readout
    fill_zero_kernel<<<(NGRAPH * 32 + 255) / 256, 256>>>(hg, NGRAPH * 32);
    fill_zero_kernel<<<1, 64>>>(cnt, NGRAPH / 4);
    pool_kernel<<<eb, 256>>>(cur, batch, M);
    pool_norm_kernel<<<(NGRAPH * HD + 255) / 256, 256>>>();
    readout_kernel<<<1, 256>>>(Wr1, br1, Wr2, br2, out);
}

// round 6
// speedup vs baseline: 1.3459x; 1.0708x over previous
#include <cuda_runtime.h>
#include <cstdint>
#include <cstddef>

// Problem constants (fixed by the reference)
#define NMAX 50000
#define EMAX 800000
#define HD   128
#define HD2  256
#define NGRAPH 64
#define NCLS 10
#define NLAYER 4
#define BN_EPS_C 1e-5f

// ---------------- scratch (device globals: no allocation allowed) ----------------
__device__ float g_hA[NMAX * HD];
__device__ float g_hB[NMAX * HD];
__device__ float g_agg[NMAX * HD];
__device__ float g_t[NMAX * HD2];
__device__ float g_z[NMAX * HD];
__device__ float g_zres[NMAX * HD];
__device__ float g_psum[HD];
__device__ float g_psq[HD];
__device__ float g_scale[HD];
__device__ float g_shift[HD];
__device__ float g_hg[NGRAPH * HD];
__device__ float g_cnt[NGRAPH];

// ---------------- utility ----------------
__global__ void fill_zero_kernel(float* __restrict__ p, int n4) {
    int i = blockIdx.x * blockDim.x + threadIdx.x;
    if (i < n4) reinterpret_cast<float4*>(p)[i] = make_float4(0.f, 0.f, 0.f, 0.f);
}

__device__ __forceinline__ uint32_t f2tf(float x) {
    uint32_t r;
    asm("cvt.rna.tf32.f32 %0, %1;" : "=r"(r) : "f"(x));
    return r;
}

__device__ __forceinline__ void mma8(float* c, const uint32_t* a, const uint32_t* b) {
    asm volatile(
        "mma.sync.aligned.m16n8k8.row.col.f32.tf32.tf32.f32 "
        "{%0,%1,%2,%3}, {%4,%5,%6,%7}, {%8,%9}, {%0,%1,%2,%3};"
        : "+f"(c[0]), "+f"(c[1]), "+f"(c[2]), "+f"(c[3])
        : "r"(a[0]), "r"(a[1]), "r"(a[2]), "r"(a[3]), "r"(b[0]), "r"(b[1]));
}

// ---------------- input projection: h = relu([x||pe] @ W_in + b_in) ----------------
__global__ void input_proj_kernel(const float* __restrict__ x, const float* __restrict__ pe,
                                  const float* __restrict__ W, const float* __restrict__ b,
                                  float* __restrict__ h, int M) {
    __shared__ float Ws[80 * 128];
    __shared__ float rows[16][80];
    for (int i = threadIdx.x; i < 80 * 128; i += 128) Ws[i] = W[i];
    int r0 = blockIdx.x * 16;
    for (int i = threadIdx.x; i < 16 * 80; i += 128) {
        int r = i / 80, c = i % 80;
        float v = 0.f;
        if (r0 + r < M)
            v = (c < 64) ? x[(size_t)(r0 + r) * 64 + c] : pe[(size_t)(r0 + r) * 16 + (c - 64)];
        rows[r][c] = v;
    }
    __syncthreads();
    int col = threadIdx.x;
    float bc = b[col];
    for (int r = 0; r < 16; r++) {
        if (r0 + r >= M) break;
        float acc = bc;
#pragma unroll 16
        for (int k = 0; k < 80; k++) acc = fmaf(rows[r][k], Ws[k * 128 + col], acc);
        h[(size_t)(r0 + r) * 128 + col] = fmaxf(acc, 0.f);
    }
}

// ---------------- edge message + aggregate ----------------
__global__ __launch_bounds__(256)
void edge_agg_kernel(const float* __restrict__ h, const int* __restrict__ ei,
                     const float* __restrict__ ea, const float* __restrict__ We,
                     const float* __restrict__ be, float* __restrict__ agg, int E) {
    int lane = threadIdx.x & 31;
    int warp = blockIdx.x * (blockDim.x >> 5) + (threadIdx.x >> 5);
    int nwarp = gridDim.x * (blockDim.x >> 5);

    float4 w[16];
#pragma unroll
    for (int k = 0; k < 16; k++)
        w[k] = *reinterpret_cast<const float4*>(We + k * 128 + lane * 4);
    float4 b4 = *reinterpret_cast<const float4*>(be + lane * 4);

    for (int e = warp; e < E; e += nwarp) {
        int src = __ldg(ei + e);
        int dst = __ldg(ei + E + e);
        const float4* eap = reinterpret_cast<const float4*>(ea + (size_t)e * 16);
        float4 a0 = eap[0], a1 = eap[1], a2 = eap[2], a3 = eap[3];
        float av[16] = {a0.x, a0.y, a0.z, a0.w, a1.x, a1.y, a1.z, a1.w,
                        a2.x, a2.y, a2.z, a2.w, a3.x, a3.y, a3.z, a3.w};
        float4 acc = b4;
#pragma unroll
        for (int k = 0; k < 16; k++) {
            acc.x = fmaf(av[k], w[k].x, acc.x);
            acc.y = fmaf(av[k], w[k].y, acc.y);
            acc.z = fmaf(av[k], w[k].z, acc.z);
            acc.w = fmaf(av[k], w[k].w, acc.w);
        }
        float4 hv = *reinterpret_cast<const float4*>(h + (size_t)src * 128 + lane * 4);
        float4 m;
        m.x = fmaxf(hv.x + acc.x, 0.f);
        m.y = fmaxf(hv.y + acc.y, 0.f);
        m.z = fmaxf(hv.z + acc.z, 0.f);
        m.w = fmaxf(hv.w + acc.w, 0.f);
        atomicAdd(reinterpret_cast<float4*>(agg + (size_t)dst * 128 + lane * 4), m);
    }
}

// ---------------- 3xTF32 tensor-core GEMM, register double-buffered ----------------
// C[M,NC] = epi(A'[M,K] @ B[K,NC] + bias)
// AMODE: 0 plain; 1 A' = (1+eps)*A + A2; 2 A' = relu(A*g_scale+g_shift) + A2 (bn1 fuse)
// RESID: 0 none; 1 += resid; 2 += relu(resid*g_scale+g_shift) + resid2 (bn1 fuse)
// STATS: accumulate column sum/sumsq of C into g_psum/g_psq (NC==128 path only)
template <int K, int NC, int AMODE, bool RELU, int RESID, bool STATS>
__global__ __launch_bounds__(256)
void gemm_tc(const float* __restrict__ A, const float* __restrict__ A2,
             const float* __restrict__ epsp, const float* __restrict__ B,
             const float* __restrict__ bias, const float* __restrict__ resid,
             const float* __restrict__ resid2, float* __restrict__ C, int M) {
    constexpr int BM = 128, BK = 16;
    constexpr int CHUNKS = K / BK;
    __shared__ uint32_t AsH[BM][BK + 4], AsL[BM][BK + 4];   // stride 20
    __shared__ uint32_t BsH[BK][128 + 8], BsL[BK][128 + 8]; // stride 136
    int tid = threadIdx.x, lane = tid & 31, warp = tid >> 5;
    int wm = warp >> 2, wn = warp & 3;
    int bm = blockIdx.y * BM, bn = blockIdx.x * 128;
    float alpha = 1.0f;
    if (AMODE == 1) alpha = 1.0f + __ldg(epsp);

    float acc[4][4][4];
#pragma unroll
    for (int i = 0; i < 4; i++)
#pragma unroll
        for (int j = 0; j < 4; j++)
#pragma unroll
            for (int q = 0; q < 4; q++) acc[i][j][q] = 0.f;

    float4 pa[2], pa2[2], pb[2];

    // prefetch loader
    auto load_tiles = [&](int k0) {
#pragma unroll
        for (int i = 0; i < 2; i++) {
            int lin = tid + i * 256;
            int r = lin >> 2, c4 = (lin & 3) * 4;
            int gr = bm + r;
            pa[i] = make_float4(0.f, 0.f, 0.f, 0.f);
            if (AMODE) pa2[i] = make_float4(0.f, 0.f, 0.f, 0.f);
            if (gr < M) {
                pa[i] = *reinterpret_cast<const float4*>(A + (size_t)gr * K + k0 + c4);
                if (AMODE)
                    pa2[i] = *reinterpret_cast<const float4*>(A2 + (size_t)gr * K + k0 + c4);
            }
        }
#pragma unroll
        for (int i = 0; i < 2; i++) {
            int lin = tid + i * 256;
            int r = lin >> 5, c4 = (lin & 31) * 4;
            pb[i] = *reinterpret_cast<const float4*>(B + (size_t)(k0 + r) * NC + bn + c4);
        }
    };

    auto store_tiles = [&](int k0) {
#pragma unroll
        for (int i = 0; i < 2; i++) {
            int lin = tid + i * 256;
            int r = lin >> 2, c4 = (lin & 3) * 4;
            float v[4] = {pa[i].x, pa[i].y, pa[i].z, pa[i].w};
            if (AMODE == 1) {
                float g[4] = {pa2[i].x, pa2[i].y, pa2[i].z, pa2[i].w};
#pragma unroll
                for (int j = 0; j < 4; j++) v[j] = fmaf(alpha, v[j], g[j]);
            } else if (AMODE == 2) {
                float g[4] = {pa2[i].x, pa2[i].y, pa2[i].z, pa2[i].w};
#pragma unroll
                for (int j = 0; j < 4; j++) {
                    int k = k0 + c4 + j;
                    v[j] = fmaxf(fmaf(v[j], g_scale[k], g_shift[k]), 0.f) + g[j];
                }
            }
            uint4 hv, lv;
            hv.x = f2tf(v[0]); lv.x = f2tf(v[0] - __uint_as_float(hv.x));
            hv.y = f2tf(v[1]); lv.y = f2tf(v[1] - __uint_as_float(hv.y));
            hv.z = f2tf(v[2]); lv.z = f2tf(v[2] - __uint_as_float(hv.z));
            hv.w = f2tf(v[3]); lv.w = f2tf(v[3] - __uint_as_float(hv.w));
            *reinterpret_cast<uint4*>(&AsH[r][c4]) = hv;
            *reinterpret_cast<uint4*>(&AsL[r][c4]) = lv;
        }
#pragma unroll
        for (int i = 0; i < 2; i++) {
            int lin = tid + i * 256;
            int r = lin >> 5, c4 = (lin & 31) * 4;
            float v[4] = {pb[i].x, pb[i].y, pb[i].z, pb[i].w};
            uint4 hv, lv;
            hv.x = f2tf(v[0]); lv.x = f2tf(v[0] - __uint_as_float(hv.x));
            hv.y = f2tf(v[1]); lv.y = f2tf(v[1] - __uint_as_float(hv.y));
            hv.z = f2tf(v[2]); lv.z = f2tf(v[2] - __uint_as_float(hv.z));
            hv.w = f2tf(v[3]); lv.w = f2tf(v[3] - __uint_as_float(hv.w));
            *reinterpret_cast<uint4*>(&BsH[r][c4]) = hv;
            *reinterpret_cast<uint4*>(&BsL[r][c4]) = lv;
        }
    };

    load_tiles(0);
#pragma unroll 1
    for (int ch = 0; ch < CHUNKS; ch++) {
        __syncthreads();
        store_tiles(ch * BK);
        __syncthreads();
        if (ch + 1 < CHUNKS) load_tiles((ch + 1) * BK);
#pragma unroll
        for (int ks = 0; ks < BK; ks += 8) {
            uint32_t aH[4][4], aL[4][4], bH[4][2], bL[4][2];
            int ar = wm * 64 + (lane >> 2);
            int ac = ks + (lane & 3);
#pragma unroll
            for (int mt = 0; mt < 4; mt++) {
                int r0 = ar + mt * 16;
                aH[mt][0] = AsH[r0][ac];
                aH[mt][1] = AsH[r0 + 8][ac];
                aH[mt][2] = AsH[r0][ac + 4];
                aH[mt][3] = AsH[r0 + 8][ac + 4];
                aL[mt][0] = AsL[r0][ac];
                aL[mt][1] = AsL[r0 + 8][ac];
                aL[mt][2] = AsL[r0][ac + 4];
                aL[mt][3] = AsL[r0 + 8][ac + 4];
            }
            int br = ks + (lane & 3);
#pragma unroll
            for (int nt = 0; nt < 4; nt++) {
                int cc = wn * 32 + nt * 8 + (lane >> 2);
                bH[nt][0] = BsH[br][cc];
                bH[nt][1] = BsH[br + 4][cc];
                bL[nt][0] = BsL[br][cc];
                bL[nt][1] = BsL[br + 4][cc];
            }
#pragma unroll
            for (int mt = 0; mt < 4; mt++)
#pragma unroll
                for (int nt = 0; nt < 4; nt++) {
                    mma8(acc[mt][nt], aH[mt], bH[nt]);
                    mma8(acc[mt][nt], aH[mt], bL[nt]);
                    mma8(acc[mt][nt], aL[mt], bH[nt]);
                }
        }
    }

    // epilogue: bias, relu, resid, store; optional BN partial stats
    float ss[8], sq[8];
#pragma unroll
    for (int j = 0; j < 8; j++) { ss[j] = 0.f; sq[j] = 0.f; }
#pragma unroll
    for (int nt = 0; nt < 4; nt++) {
        int cl = wn * 32 + nt * 8 + (lane & 3) * 2;  // local col (for scale/stats, NC==128 paths)
        int c = bn + cl;                              // global col
        float b0 = __ldg(bias + c), b1 = __ldg(bias + c + 1);
        float sc0 = 0.f, sc1 = 0.f, sh0 = 0.f, sh1 = 0.f;
        if (RESID == 2) {
            sc0 = g_scale[cl]; sc1 = g_scale[cl + 1];
            sh0 = g_shift[cl]; sh1 = g_shift[cl + 1];
        }
#pragma unroll
        for (int mt = 0; mt < 4; mt++) {
#pragma unroll
            for (int half = 0; half < 2; half++) {
                int r = bm + wm * 64 + mt * 16 + (lane >> 2) + half * 8;
                if (r < M) {
                    float v0 = acc[mt][nt][half * 2 + 0] + b0;
                    float v1 = acc[mt][nt][half * 2 + 1] + b1;
                    if (RELU) { v0 = fmaxf(v0, 0.f); v1 = fmaxf(v1, 0.f); }
                    if (RESID == 1) {
                        float2 rv = *reinterpret_cast<const float2*>(resid + (size_t)r * NC + c);
                        v0 += rv.x;
                        v1 += rv.y;
                    } else if (RESID == 2) {
                        float2 zv = *reinterpret_cast<const float2*>(resid + (size_t)r * NC + c);
                        float2 hv = *reinterpret_cast<const float2*>(resid2 + (size_t)r * NC + c);
                        v0 += fmaxf(fmaf(zv.x, sc0, sh0), 0.f) + hv.x;
                        v1 += fmaxf(fmaf(zv.y, sc1, sh1), 0.f) + hv.y;
                    }
                    *reinterpret_cast<float2*>(C + (size_t)r * NC + c) = make_float2(v0, v1);
                    if (STATS) {
                        ss[nt * 2] += v0;
                        ss[nt * 2 + 1] += v1;
                        sq[nt * 2] = fmaf(v0, v0, sq[nt * 2]);
                        sq[nt * 2 + 1] = fmaf(v1, v1, sq[nt * 2 + 1]);
                    }
                }
            }
        }
    }
    if (STATS) {
#pragma unroll
        for (int j = 0; j < 8; j++) {
#pragma unroll
            for (int o = 16; o >= 4; o >>= 1) {
                ss[j] += __shfl_xor_sync(0xFFFFFFFFu, ss[j], o);
                sq[j] += __shfl_xor_sync(0xFFFFFFFFu, sq[j], o);
            }
        }
        if ((lane >> 2) == 0) {
#pragma unroll
            for (int nt = 0; nt < 4; nt++) {
                int c = wn * 32 + nt * 8 + lane * 2;
                atomicAdd(&g_psum[c], ss[nt * 2]);
                atomicAdd(&g_psum[c + 1], ss[nt * 2 + 1]);
                atomicAdd(&g_psq[c], sq[nt * 2]);
                atomicAdd(&g_psq[c + 1], sq[nt * 2 + 1]);
            }
        }
    }
}

// ---------------- batch norm finalize (stats from GEMM epilogues) ----------------
__global__ void bn_finalize_kernel(const float* __restrict__ g, const float* __restrict__ b,
                                   int M) {
    int col = threadIdx.x;  // 128 threads
    float s = g_psum[col], q = g_psq[col];
    g_psum[col] = 0.f;  // re-arm for next accumulation (graph-replay deterministic)
    g_psq[col] = 0.f;
    float mean = s / (float)M;
    float var = q / (float)M - mean * mean;
    float sc = g[col] * rsqrtf(var + BN_EPS_C);
    g_scale[col] = sc;
    g_shift[col] = b[col] - mean * sc;
}

// hn = bn(s)
__global__ void bn2_apply_kernel(const float* __restrict__ s, float* __restrict__ hn, int M) {
    int i = blockIdx.x * blockDim.x + threadIdx.x;
    if (i >= M * 32) return;
    int c = i & 31;
    float4 sc = *reinterpret_cast<const float4*>(g_scale + c * 4);
    float4 sh = *reinterpret_cast<const float4*>(g_shift + c * 4);
    float4 sv = reinterpret_cast<const float4*>(s)[i];
    float4 o;
    o.x = fmaf(sv.x, sc.x, sh.x);
    o.y = fmaf(sv.y, sc.y, sh.y);
    o.z = fmaf(sv.z, sc.z, sh.z);
    o.w = fmaf(sv.w, sc.w, sh.w);
    reinterpret_cast<float4*>(hn)[i] = o;
}

// ---------------- global mean pool (segmented: batch is sorted) + readout ----------------
__global__ void pool_kernel(const float* __restrict__ h, const int* __restrict__ batch, int M) {
    constexpr int R = 64;
    __shared__ int sb[R];
    int r0 = blockIdx.x * R;
    int nr = min(R, M - r0);
    int c = threadIdx.x;  // 128
    if (nr <= 0) return;
    for (int i = c; i < nr; i += 128) sb[i] = batch[r0 + i];
    __syncthreads();
    float acc = 0.f;
    int curg = sb[0];
    for (int r = 0; r < nr; r++) {
        int g = sb[r];
        if (g != curg) {
            atomicAdd(&g_hg[curg * HD + c], acc);
            acc = 0.f;
            curg = g;
        }
        acc += h[(size_t)(r0 + r) * HD + c];
    }
    atomicAdd(&g_hg[curg * HD + c], acc);
    if (c == 0) {
        int gg = sb[0], rl = 0;
        for (int r = 0; r < nr; r++) {
            if (sb[r] != gg) {
                atomicAdd(&g_cnt[gg], (float)rl);
                gg = sb[r];
                rl = 0;
            }
            rl++;
        }
        atomicAdd(&g_cnt[gg], (float)rl);
    }
}

__global__ void pool_norm_kernel() {
    int i = blockIdx.x * blockDim.x + threadIdx.x;
    if (i < NGRAPH * HD) g_hg[i] /= fmaxf(g_cnt[i >> 7], 1.0f);
}

__global__ void readout_kernel(const float* __restrict__ W1, const float* __restrict__ b1,
                               const float* __restrict__ W2, const float* __restrict__ b2,
                               float* __restrict__ out) {
    __shared__ float u[NGRAPH * HD];
    int tid = threadIdx.x;  // 256
    for (int i = tid; i < NGRAPH * HD; i += 256) {
        int g = i >> 7, c = i & 127;
        float acc = b1[c];
#pragma unroll 8
        for (int k = 0; k < 128; k++) acc = fmaf(g_hg[g * 128 + k], W1[k * 128 + c], acc);
        u[i] = fmaxf(acc, 0.f);
    }
    __syncthreads();
    for (int i = tid; i < NGRAPH * NCLS; i += 256) {
        int g = i / NCLS, c = i % NCLS;
        float acc = b2[c];
#pragma unroll 8
        for (int k = 0; k < 128; k++) acc = fmaf(u[g * 128 + k], W2[k * NCLS + c], acc);
        out[i] = acc;
    }
}

// ---------------- launch ----------------
extern "C" void kernel_launch(void* const* d_in, const int* in_sizes, int n_in,
                              void* d_out, int out_size) {
    const float* x = (const float*)d_in[0];
    const float* pe = (const float*)d_in[1];
    const int* ei = (const int*)d_in[2];
    const float* ea = (const float*)d_in[3];
    const int* batch = (const int*)d_in[4];
    const float* W_in = (const float*)d_in[5];
    const float* b_in = (const float*)d_in[6];
    const float* We = (const float*)d_in[7];
    const float* bee = (const float*)d_in[8];
    const float* eps = (const float*)d_in[9];
    const float* W1g = (const float*)d_in[10];
    const float* b1g = (const float*)d_in[11];
    const float* W2g = (const float*)d_in[12];
    const float* b2g = (const float*)d_in[13];
    const float* bn1g = (const float*)d_in[14];
    const float* bn1b = (const float*)d_in[15];
    const float* W1f = (const float*)d_in[16];
    const float* b1f = (const float*)d_in[17];
    const float* W2f = (const float*)d_in[18];
    const float* b2f = (const float*)d_in[19];
    const float* bn2g = (const float*)d_in[20];
    const float* bn2b = (const float*)d_in[21];
    const float* Wr1 = (const float*)d_in[22];
    const float* br1 = (const float*)d_in[23];
    const float* Wr2 = (const float*)d_in[24];
    const float* br2 = (const float*)d_in[25];
    float* out = (float*)d_out;

    int M = in_sizes[0] / 64;  // N nodes
    int E = in_sizes[2] / 2;   // edges

    float *hA, *hB, *agg, *tb, *zb, *zres, *hg, *cnt, *psum, *psq;
    cudaGetSymbolAddress((void**)&hA, g_hA);
    cudaGetSymbolAddress((void**)&hB, g_hB);
    cudaGetSymbolAddress((void**)&agg, g_agg);
    cudaGetSymbolAddress((void**)&tb, g_t);
    cudaGetSymbolAddress((void**)&zb, g_z);
    cudaGetSymbolAddress((void**)&zres, g_zres);
    cudaGetSymbolAddress((void**)&hg, g_hg);
    cudaGetSymbolAddress((void**)&cnt, g_cnt);
    cudaGetSymbolAddress((void**)&psum, g_psum);
    cudaGetSymbolAddress((void**)&psq, g_psq);

    // re-arm BN partial-sum accumulators
    fill_zero_kernel<<<1, 64>>>(psum, HD / 4);
    fill_zero_kernel<<<1, 64>>>(psq, HD / 4);

    input_proj_kernel<<<(M + 15) / 16, 128>>>(x, pe, W_in, b_in, hA, M);

    float* cur = hA;
    float* nxt = hB;
    int n4 = M * 32;
    int ewBlocks = 2048;
    dim3 gW(2, (M + 127) / 128);  // NC=256
    dim3 gN(1, (M + 127) / 128);  // NC=128
    int eb = (n4 + 255) / 256;

    for (int l = 0; l < NLAYER; l++) {
        // GINEConv aggregate
        fill_zero_kernel<<<eb, 256>>>(agg, n4);
        edge_agg_kernel<<<ewBlocks, 256>>>(cur, ei, ea, We + l * 16 * 128, bee + l * 128, agg, E);
        // GIN MLP: t = relu(((1+eps)h + agg) @ W1 + b1); z = t @ W2 + b2 (+BN1 stats)
        gemm_tc<128, 256, 1, true, 0, false><<<gW, 256>>>(
            cur, agg, eps + l, W1g + (size_t)l * 128 * 256, b1g + l * 256, nullptr, nullptr, tb, M);
        gemm_tc<256, 128, 0, false, 0, true><<<gN, 256>>>(
            tb, nullptr, nullptr, W2g + (size_t)l * 256 * 128, b2g + l * 128, nullptr, nullptr, zb, M);
        bn_finalize_kernel<<<1, 128>>>(bn1g + l * 128, bn1b + l * 128, M);
        // FFN: zres = relu(bn1(z)) + h computed on the fly (AMODE=2 / RESID=2)
        // t = relu(zres @ W1f + b1f); z2 = t @ W2f + b2f + zres (+BN2 stats)
        gemm_tc<128, 256, 2, true, 0, false><<<gW, 256>>>(
            zb, cur, nullptr, W1f + (size_t)l * 128 * 256, b1f + l * 256, nullptr, nullptr, tb, M);
        gemm_tc<256, 128, 0, false, 2, true><<<gN, 256>>>(
            tb, nullptr, nullptr, W2f + (size_t)l * 256 * 128, b2f + l * 128, zb, cur, zres, M);
        bn_finalize_kernel<<<1, 128>>>(bn2g + l * 128, bn2b + l * 128, M);
        bn2_apply_kernel<<<eb, 256>>>(zres, nxt, M);
        float* tmp = cur; cur = nxt; nxt = tmp;
    }

    // Global mean pool + readout
    fill_zero_kernel<<<(NGRAPH * 32 + 255) / 256, 256>>>(hg, NGRAPH * 32);
    fill_zero_kernel<<<1, 64>>>(cnt, NGRAPH / 4);
    pool_kernel<<<(M + 63) / 64, 128>>>(cur, batch, M);
    pool_norm_kernel<<<(NGRAPH * HD + 255) / 256, 256>>>();
    readout_kernel<<<1, 256>>>(Wr1, br1, Wr2, br2, out);
}

// round 7
// speedup vs baseline: 1.4022x; 1.0418x over previous
#include <cuda_runtime.h>
#include <cstdint>
#include <cstddef>

// Problem constants (fixed by the reference)
#define NMAX 50000
#define EMAX 800000
#define HD   128
#define HD2  256
#define NGRAPH 64
#define NCLS 10
#define NLAYER 4
#define BN_EPS_C 1e-5f

// ---------------- scratch (device globals: no allocation allowed) ----------------
__device__ float g_hA[NMAX * HD];
__device__ float g_hB[NMAX * HD];
__device__ float g_agg[NMAX * HD];
__device__ float g_t[NMAX * HD2];
__device__ float g_z[NMAX * HD];
__device__ float g_psum[HD];
__device__ float g_psq[HD];
__device__ float g_scale1[HD];
__device__ float g_shift1[HD];
__device__ float g_scale2[HD];
__device__ float g_shift2[HD];
__device__ float g_hg[NGRAPH * HD];
__device__ float g_cnt[NGRAPH];
// CSR scratch
__device__ int g_deg[NMAX];
__device__ int g_rp[NMAX + 1];
__device__ int g_cursor[NMAX];
__device__ int g_esrc[EMAX];
__device__ float g_eas[EMAX * 16];
// pre-split tf32 weights: [W1g | W2g | W1f | W2f], each L*128*256 = 131072
__device__ uint32_t g_WH[4 * NLAYER * 32768];
__device__ uint32_t g_WL[4 * NLAYER * 32768];

// ---------------- utility ----------------
__global__ void fill_zero_kernel(float* __restrict__ p, int n4) {
    int i = blockIdx.x * blockDim.x + threadIdx.x;
    if (i < n4) reinterpret_cast<float4*>(p)[i] = make_float4(0.f, 0.f, 0.f, 0.f);
}

__global__ void init_scale2_kernel() {
    int i = threadIdx.x;  // 128
    g_scale2[i] = 1.0f;
    g_shift2[i] = 0.0f;
}

__device__ __forceinline__ uint32_t f2tf(float x) {
    uint32_t r;
    asm("cvt.rna.tf32.f32 %0, %1;" : "=r"(r) : "f"(x));
    return r;
}

__global__ void split_w_kernel(const float* __restrict__ W, uint32_t* __restrict__ WH,
                               uint32_t* __restrict__ WL, int n) {
    int i = blockIdx.x * blockDim.x + threadIdx.x;
    if (i >= n) return;
    float v = W[i];
    uint32_t h = f2tf(v);
    WH[i] = h;
    WL[i] = f2tf(v - __uint_as_float(h));
}

__device__ __forceinline__ void mma8(float* c, const uint32_t* a, const uint32_t* b) {
    asm volatile(
        "mma.sync.aligned.m16n8k8.row.col.f32.tf32.tf32.f32 "
        "{%0,%1,%2,%3}, {%4,%5,%6,%7}, {%8,%9}, {%0,%1,%2,%3};"
        : "+f"(c[0]), "+f"(c[1]), "+f"(c[2]), "+f"(c[3])
        : "r"(a[0]), "r"(a[1]), "r"(a[2]), "r"(a[3]), "r"(b[0]), "r"(b[1]));
}

// ---------------- CSR build (per call; atomic order nondeterminism only permutes
// float summation order, equivalent within tolerance — same as the old atomics) ----
__global__ void hist_kernel(const int* __restrict__ ei, int E, int* __restrict__ deg) {
    int e = blockIdx.x * blockDim.x + threadIdx.x;
    if (e < E) atomicAdd(&deg[ei[E + e]], 1);
}

__global__ void scan_kernel(const int* __restrict__ deg, int* __restrict__ rp, int n) {
    __shared__ int buf[1024];
    __shared__ int carry;
    int tid = threadIdx.x;
    if (tid == 0) { carry = 0; rp[0] = 0; }
    __syncthreads();
    for (int base = 0; base < n; base += 1024) {
        int v = (base + tid < n) ? deg[base + tid] : 0;
        buf[tid] = v;
        __syncthreads();
        for (int o = 1; o < 1024; o <<= 1) {
            int t = (tid >= o) ? buf[tid - o] : 0;
            __syncthreads();
            buf[tid] += t;
            __syncthreads();
        }
        if (base + tid < n) rp[base + tid + 1] = carry + buf[tid];
        __syncthreads();
        if (tid == 0) carry += buf[1023];
        __syncthreads();
    }
}

__global__ void copy_int_kernel(int* __restrict__ dst, const int* __restrict__ src, int n) {
    int i = blockIdx.x * blockDim.x + threadIdx.x;
    if (i < n) dst[i] = src[i];
}

__global__ void scatter_kernel(const int* __restrict__ ei, const float* __restrict__ ea,
                               int* __restrict__ cursor, int* __restrict__ esrc,
                               float* __restrict__ eas, int E) {
    int e = blockIdx.x * blockDim.x + threadIdx.x;
    if (e >= E) return;
    int dst = ei[E + e];
    int pos = atomicAdd(&cursor[dst], 1);
    esrc[pos] = ei[e];
    float4* d = reinterpret_cast<float4*>(eas + (size_t)pos * 16);
    const float4* s = reinterpret_cast<const float4*>(ea + (size_t)e * 16);
    d[0] = s[0]; d[1] = s[1]; d[2] = s[2]; d[3] = s[3];
}

// ---------------- input projection: h = relu([x||pe] @ W_in + b_in) ----------------
__global__ void input_proj_kernel(const float* __restrict__ x, const float* __restrict__ pe,
                                  const float* __restrict__ W, const float* __restrict__ b,
                                  float* __restrict__ h, int M) {
    __shared__ float Ws[80 * 128];
    __shared__ float rows[16][80];
    for (int i = threadIdx.x; i < 80 * 128; i += 128) Ws[i] = W[i];
    int r0 = blockIdx.x * 16;
    for (int i = threadIdx.x; i < 16 * 80; i += 128) {
        int r = i / 80, c = i % 80;
        float v = 0.f;
        if (r0 + r < M)
            v = (c < 64) ? x[(size_t)(r0 + r) * 64 + c] : pe[(size_t)(r0 + r) * 16 + (c - 64)];
        rows[r][c] = v;
    }
    __syncthreads();
    int col = threadIdx.x;
    float bc = b[col];
    for (int r = 0; r < 16; r++) {
        if (r0 + r >= M) break;
        float acc = bc;
#pragma unroll 16
        for (int k = 0; k < 80; k++) acc = fmaf(rows[r][k], Ws[k * 128 + col], acc);
        h[(size_t)(r0 + r) * 128 + col] = fmaxf(acc, 0.f);
    }
}

// ---------------- pull-based node aggregate (CSR, no fp atomics) ----------------
// agg[i] = sum over in-edges p: relu( bn2(S[src_p]) + (eas[p] @ We + be) )
__global__ __launch_bounds__(256)
void node_agg_kernel(const float* __restrict__ S, const int* __restrict__ rp,
                     const int* __restrict__ esrc, const float* __restrict__ eas,
                     const float* __restrict__ We, const float* __restrict__ be,
                     float* __restrict__ agg, int M) {
    int lane = threadIdx.x & 31;
    int warp = blockIdx.x * (blockDim.x >> 5) + (threadIdx.x >> 5);
    int nwarp = gridDim.x * (blockDim.x >> 5);

    float4 w[16];
#pragma unroll
    for (int k = 0; k < 16; k++)
        w[k] = *reinterpret_cast<const float4*>(We + k * 128 + lane * 4);
    float4 b4 = *reinterpret_cast<const float4*>(be + lane * 4);
    float4 sc = *reinterpret_cast<const float4*>(g_scale2 + lane * 4);
    float4 sh = *reinterpret_cast<const float4*>(g_shift2 + lane * 4);

    for (int i = warp; i < M; i += nwarp) {
        int p0 = __ldg(rp + i), p1 = __ldg(rp + i + 1);
        float4 acc = make_float4(0.f, 0.f, 0.f, 0.f);
        for (int p = p0; p < p1; p++) {
            int src = __ldg(esrc + p);
            const float4* eap = reinterpret_cast<const float4*>(eas + (size_t)p * 16);
            float4 a0 = eap[0], a1 = eap[1], a2 = eap[2], a3 = eap[3];
            float av[16] = {a0.x, a0.y, a0.z, a0.w, a1.x, a1.y, a1.z, a1.w,
                            a2.x, a2.y, a2.z, a2.w, a3.x, a3.y, a3.z, a3.w};
            float4 el = b4;
#pragma unroll
            for (int k = 0; k < 16; k++) {
                el.x = fmaf(av[k], w[k].x, el.x);
                el.y = fmaf(av[k], w[k].y, el.y);
                el.z = fmaf(av[k], w[k].z, el.z);
                el.w = fmaf(av[k], w[k].w, el.w);
            }
            float4 hv = *reinterpret_cast<const float4*>(S + (size_t)src * 128 + lane * 4);
            acc.x += fmaxf(fmaf(hv.x, sc.x, sh.x) + el.x, 0.f);
            acc.y += fmaxf(fmaf(hv.y, sc.y, sh.y) + el.y, 0.f);
            acc.z += fmaxf(fmaf(hv.z, sc.z, sh.z) + el.z, 0.f);
            acc.w += fmaxf(fmaf(hv.w, sc.w, sh.w) + el.w, 0.f);
        }
        *reinterpret_cast<float4*>(agg + (size_t)i * 128 + lane * 4) = acc;
    }
}

// ---------------- 3xTF32 tensor-core GEMM (pre-split B, fused BN) ----------------
// C[M,NC] = epi(A'[M,K] @ B[K,NC] + bias)
// AMODE: 0: A' = A
//        1: A' = (1+eps)*bn2(A) + A2                 [GIN combine]
//        2: A' = relu(bn1(A)) + bn2(A2)              [FFN input]
// RESID: 0 none; 2: C += relu(bn1(resid)) + bn2(resid2)   [FFN residual]
// STATS: accumulate column sum/sumsq of C into g_psum/g_psq (NC==128 only)
template <int K, int NC, int AMODE, bool RELU, int RESID, bool STATS>
__global__ __launch_bounds__(256)
void gemm_tc(const float* __restrict__ A, const float* __restrict__ A2,
             const float* __restrict__ epsp, const uint32_t* __restrict__ BH,
             const uint32_t* __restrict__ BL, const float* __restrict__ bias,
             const float* __restrict__ resid, const float* __restrict__ resid2,
             float* __restrict__ C, int M) {
    constexpr int BM = 128, BK = 16;
    constexpr int CHUNKS = K / BK;
    __shared__ uint32_t AsH[BM][BK + 4], AsL[BM][BK + 4];   // stride 20
    __shared__ uint32_t BsH[BK][128 + 8], BsL[BK][128 + 8]; // stride 136
    int tid = threadIdx.x, lane = tid & 31, warp = tid >> 5;
    int wm = warp >> 2, wn = warp & 3;
    int bm = blockIdx.y * BM, bn = blockIdx.x * 128;
    float alpha = 1.0f;
    if (AMODE == 1) alpha = 1.0f + __ldg(epsp);

    float acc[4][4][4];
#pragma unroll
    for (int i = 0; i < 4; i++)
#pragma unroll
        for (int j = 0; j < 4; j++)
#pragma unroll
            for (int q = 0; q < 4; q++) acc[i][j][q] = 0.f;

    float4 pa[2], pa2[2];
    uint4 pbH[2], pbL[2];

    auto load_tiles = [&](int k0) {
#pragma unroll
        for (int i = 0; i < 2; i++) {
            int lin = tid + i * 256;
            int r = lin >> 2, c4 = (lin & 3) * 4;
            int gr = bm + r;
            pa[i] = make_float4(0.f, 0.f, 0.f, 0.f);
            if (AMODE) pa2[i] = make_float4(0.f, 0.f, 0.f, 0.f);
            if (gr < M) {
                pa[i] = *reinterpret_cast<const float4*>(A + (size_t)gr * K + k0 + c4);
                if (AMODE)
                    pa2[i] = *reinterpret_cast<const float4*>(A2 + (size_t)gr * K + k0 + c4);
            }
        }
#pragma unroll
        for (int i = 0; i < 2; i++) {
            int lin = tid + i * 256;
            int r = lin >> 5, c4 = (lin & 31) * 4;
            pbH[i] = *reinterpret_cast<const uint4*>(BH + (size_t)(k0 + r) * NC + bn + c4);
            pbL[i] = *reinterpret_cast<const uint4*>(BL + (size_t)(k0 + r) * NC + bn + c4);
        }
    };

    auto store_tiles = [&](int k0) {
#pragma unroll
        for (int i = 0; i < 2; i++) {
            int lin = tid + i * 256;
            int r = lin >> 2, c4 = (lin & 3) * 4;
            float v[4] = {pa[i].x, pa[i].y, pa[i].z, pa[i].w};
            if (AMODE == 1) {
                float g[4] = {pa2[i].x, pa2[i].y, pa2[i].z, pa2[i].w};
#pragma unroll
                for (int j = 0; j < 4; j++) {
                    int k = k0 + c4 + j;
                    v[j] = fmaf(alpha, fmaf(v[j], g_scale2[k], g_shift2[k]), g[j]);
                }
            } else if (AMODE == 2) {
                float g[4] = {pa2[i].x, pa2[i].y, pa2[i].z, pa2[i].w};
#pragma unroll
                for (int j = 0; j < 4; j++) {
                    int k = k0 + c4 + j;
                    v[j] = fmaxf(fmaf(v[j], g_scale1[k], g_shift1[k]), 0.f) +
                           fmaf(g[j], g_scale2[k], g_shift2[k]);
                }
            }
            uint4 hv, lv;
            hv.x = f2tf(v[0]); lv.x = f2tf(v[0] - __uint_as_float(hv.x));
            hv.y = f2tf(v[1]); lv.y = f2tf(v[1] - __uint_as_float(hv.y));
            hv.z = f2tf(v[2]); lv.z = f2tf(v[2] - __uint_as_float(hv.z));
            hv.w = f2tf(v[3]); lv.w = f2tf(v[3] - __uint_as_float(hv.w));
            *reinterpret_cast<uint4*>(&AsH[r][c4]) = hv;
            *reinterpret_cast<uint4*>(&AsL[r][c4]) = lv;
        }
#pragma unroll
        for (int i = 0; i < 2; i++) {
            int lin = tid + i * 256;
            int r = lin >> 5, c4 = (lin & 31) * 4;
            *reinterpret_cast<uint4*>(&BsH[r][c4]) = pbH[i];
            *reinterpret_cast<uint4*>(&BsL[r][c4]) = pbL[i];
        }
    };

    load_tiles(0);
#pragma unroll 1
    for (int ch = 0; ch < CHUNKS; ch++) {
        __syncthreads();
        store_tiles(ch * BK);
        __syncthreads();
        if (ch + 1 < CHUNKS) load_tiles((ch + 1) * BK);
#pragma unroll
        for (int ks = 0; ks < BK; ks += 8) {
            uint32_t aH[4][4], aL[4][4], bH[4][2], bL[4][2];
            int ar = wm * 64 + (lane >> 2);
            int ac = ks + (lane & 3);
#pragma unroll
            for (int mt = 0; mt < 4; mt++) {
                int r0 = ar + mt * 16;
                aH[mt][0] = AsH[r0][ac];
                aH[mt][1] = AsH[r0 + 8][ac];
                aH[mt][2] = AsH[r0][ac + 4];
                aH[mt][3] = AsH[r0 + 8][ac + 4];
                aL[mt][0] = AsL[r0][ac];
                aL[mt][1] = AsL[r0 + 8][ac];
                aL[mt][2] = AsL[r0][ac + 4];
                aL[mt][3] = AsL[r0 + 8][ac + 4];
            }
            int br = ks + (lane & 3);
#pragma unroll
            for (int nt = 0; nt < 4; nt++) {
                int cc = wn * 32 + nt * 8 + (lane >> 2);
                bH[nt][0] = BsH[br][cc];
                bH[nt][1] = BsH[br + 4][cc];
                bL[nt][0] = BsL[br][cc];
                bL[nt][1] = BsL[br + 4][cc];
            }
#pragma unroll
            for (int mt = 0; mt < 4; mt++)
#pragma unroll
                for (int nt = 0; nt < 4; nt++) {
                    mma8(acc[mt][nt], aH[mt], bH[nt]);
                    mma8(acc[mt][nt], aH[mt], bL[nt]);
                    mma8(acc[mt][nt], aL[mt], bH[nt]);
                }
        }
    }

    // epilogue
    float ss[8], sq[8];
#pragma unroll
    for (int j = 0; j < 8; j++) { ss[j] = 0.f; sq[j] = 0.f; }
#pragma unroll
    for (int nt = 0; nt < 4; nt++) {
        int cl = wn * 32 + nt * 8 + (lane & 3) * 2;  // local col (NC==128 paths)
        int c = bn + cl;
        float b0 = __ldg(bias + c), b1 = __ldg(bias + c + 1);
        float s10 = 0.f, s11 = 0.f, h10 = 0.f, h11 = 0.f;
        float s20 = 0.f, s21 = 0.f, h20 = 0.f, h21 = 0.f;
        if (RESID == 2) {
            s10 = g_scale1[cl]; s11 = g_scale1[cl + 1];
            h10 = g_shift1[cl]; h11 = g_shift1[cl + 1];
            s20 = g_scale2[cl]; s21 = g_scale2[cl + 1];
            h20 = g_shift2[cl]; h21 = g_shift2[cl + 1];
        }
#pragma unroll
        for (int mt = 0; mt < 4; mt++) {
#pragma unroll
            for (int half = 0; half < 2; half++) {
                int r = bm + wm * 64 + mt * 16 + (lane >> 2) + half * 8;
                if (r < M) {
                    float v0 = acc[mt][nt][half * 2 + 0] + b0;
                    float v1 = acc[mt][nt][half * 2 + 1] + b1;
                    if (RELU) { v0 = fmaxf(v0, 0.f); v1 = fmaxf(v1, 0.f); }
                    if (RESID == 2) {
                        float2 zv = *reinterpret_cast<const float2*>(resid + (size_t)r * NC + c);
                        float2 sv = *reinterpret_cast<const float2*>(resid2 + (size_t)r * NC + c);
                        v0 += fmaxf(fmaf(zv.x, s10, h10), 0.f) + fmaf(sv.x, s20, h20);
                        v1 += fmaxf(fmaf(zv.y, s11, h11), 0.f) + fmaf(sv.y, s21, h21);
                    }
                    *reinterpret_cast<float2*>(C + (size_t)r * NC + c) = make_float2(v0, v1);
                    if (STATS) {
                        ss[nt * 2] += v0;
                        ss[nt * 2 + 1] += v1;
                        sq[nt * 2] = fmaf(v0, v0, sq[nt * 2]);
                        sq[nt * 2 + 1] = fmaf(v1, v1, sq[nt * 2 + 1]);
                    }
                }
            }
        }
    }
    if (STATS) {
#pragma unroll
        for (int j = 0; j < 8; j++) {
#pragma unroll
            for (int o = 16; o >= 4; o >>= 1) {
                ss[j] += __shfl_xor_sync(0xFFFFFFFFu, ss[j], o);
                sq[j] += __shfl_xor_sync(0xFFFFFFFFu, sq[j], o);
            }
        }
        if ((lane >> 2) == 0) {
#pragma unroll
            for (int nt = 0; nt < 4; nt++) {
                int c = wn * 32 + nt * 8 + lane * 2;
                atomicAdd(&g_psum[c], ss[nt * 2]);
                atomicAdd(&g_psum[c + 1], ss[nt * 2 + 1]);
                atomicAdd(&g_psq[c], sq[nt * 2]);
                atomicAdd(&g_psq[c + 1], sq[nt * 2 + 1]);
            }
        }
    }
}

// ---------------- batch norm finalize ----------------
__global__ void bn_finalize_kernel(const float* __restrict__ g, const float* __restrict__ b,
                                   int M, float* __restrict__ outSc, float* __restrict__ outSh) {
    int col = threadIdx.x;  // 128
    float s = g_psum[col], q = g_psq[col];
    g_psum[col] = 0.f;
    g_psq[col] = 0.f;
    float mean = s / (float)M;
    float var = q / (float)M - mean * mean;
    float sc = g[col] * rsqrtf(var + BN_EPS_C);
    outSc[col] = sc;
    outSh[col] = b[col] - mean * sc;
}

// ---------------- global mean pool (segmented, bn2 fused) + readout ----------------
__global__ void pool_kernel(const float* __restrict__ h, const int* __restrict__ batch, int M) {
    constexpr int R = 64;
    __shared__ int sb[R];
    int r0 = blockIdx.x * R;
    int nr = min(R, M - r0);
    int c = threadIdx.x;  // 128
    if (nr <= 0) return;
    for (int i = c; i < nr; i += 128) sb[i] = batch[r0 + i];
    __syncthreads();
    float sc = g_scale2[c], sh = g_shift2[c];
    float acc = 0.f;
    int curg = sb[0];
    for (int r = 0; r < nr; r++) {
        int g = sb[r];
        if (g != curg) {
            atomicAdd(&g_hg[curg * HD + c], acc);
            acc = 0.f;
            curg = g;
        }
        acc += fmaf(h[(size_t)(r0 + r) * HD + c], sc, sh);
    }
    atomicAdd(&g_hg[curg * HD + c], acc);
    if (c == 0) {
        int gg = sb[0], rl = 0;
        for (int r = 0; r < nr; r++) {
            if (sb[r] != gg) {
                atomicAdd(&g_cnt[gg], (float)rl);
                gg = sb[r];
                rl = 0;
            }
            rl++;
        }
        atomicAdd(&g_cnt[gg], (float)rl);
    }
}

__global__ void pool_norm_kernel() {
    int i = blockIdx.x * blockDim.x + threadIdx.x;
    if (i < NGRAPH * HD) g_hg[i] /= fmaxf(g_cnt[i >> 7], 1.0f);
}

__global__ void readout_kernel(const float* __restrict__ W1, const float* __restrict__ b1,
                               const float* __restrict__ W2, const float* __restrict__ b2,
                               float* __restrict__ out) {
    __shared__ float u[NGRAPH * HD];
    int tid = threadIdx.x;  // 256
    for (int i = tid; i < NGRAPH * HD; i += 256) {
        int g = i >> 7, c = i & 127;
        float acc = b1[c];
#pragma unroll 8
        for (int k = 0; k < 128; k++) acc = fmaf(g_hg[g * 128 + k], W1[k * 128 + c], acc);
        u[i] = fmaxf(acc, 0.f);
    }
    __syncthreads();
    for (int i = tid; i < NGRAPH * NCLS; i += 256) {
        int g = i / NCLS, c = i % NCLS;
        float acc = b2[c];
#pragma unroll 8
        for (int k = 0; k < 128; k++) acc = fmaf(u[g * 128 + k], W2[k * NCLS + c], acc);
        out[i] = acc;
    }
}

// ---------------- launch ----------------
extern "C" void kernel_launch(void* const* d_in, const int* in_sizes, int n_in,
                              void* d_out, int out_size) {
    const float* x = (const float*)d_in[0];
    const float* pe = (const float*)d_in[1];
    const int* ei = (const int*)d_in[2];
    const float* ea = (const float*)d_in[3];
    const int* batch = (const int*)d_in[4];
    const float* W_in = (const float*)d_in[5];
    const float* b_in = (const float*)d_in[6];
    const float* We = (const float*)d_in[7];
    const float* bee = (const float*)d_in[8];
    const float* eps = (const float*)d_in[9];
    const float* W1g = (const float*)d_in[10];
    const float* b1g = (const float*)d_in[11];
    const float* W2g = (const float*)d_in[12];
    const float* b2g = (const float*)d_in[13];
    const float* bn1g = (const float*)d_in[14];
    const float* bn1b = (const float*)d_in[15];
    const float* W1f = (const float*)d_in[16];
    const float* b1f = (const float*)d_in[17];
    const float* W2f = (const float*)d_in[18];
    const float* b2f = (const float*)d_in[19];
    const float* bn2g = (const float*)d_in[20];
    const float* bn2b = (const float*)d_in[21];
    const float* Wr1 = (const float*)d_in[22];
    const float* br1 = (const float*)d_in[23];
    const float* Wr2 = (const float*)d_in[24];
    const float* br2 = (const float*)d_in[25];
    float* out = (float*)d_out;

    int M = in_sizes[0] / 64;  // N nodes
    int E = in_sizes[2] / 2;   // edges

    float *hA, *hB, *agg, *tb, *zb, *hg, *cnt, *psum, *psq, *sc1, *sh1, *sc2, *sh2;
    int *deg, *rp, *cursor, *esrc;
    float* eas;
    uint32_t *WH, *WL;
    cudaGetSymbolAddress((void**)&hA, g_hA);
    cudaGetSymbolAddress((void**)&hB, g_hB);
    cudaGetSymbolAddress((void**)&agg, g_agg);
    cudaGetSymbolAddress((void**)&tb, g_t);
    cudaGetSymbolAddress((void**)&zb, g_z);
    cudaGetSymbolAddress((void**)&hg, g_hg);
    cudaGetSymbolAddress((void**)&cnt, g_cnt);
    cudaGetSymbolAddress((void**)&psum, g_psum);
    cudaGetSymbolAddress((void**)&psq, g_psq);
    cudaGetSymbolAddress((void**)&sc1, g_scale1);
    cudaGetSymbolAddress((void**)&sh1, g_shift1);
    cudaGetSymbolAddress((void**)&sc2, g_scale2);
    cudaGetSymbolAddress((void**)&sh2, g_shift2);
    cudaGetSymbolAddress((void**)&deg, g_deg);
    cudaGetSymbolAddress((void**)&rp, g_rp);
    cudaGetSymbolAddress((void**)&cursor, g_cursor);
    cudaGetSymbolAddress((void**)&esrc, g_esrc);
    cudaGetSymbolAddress((void**)&eas, g_eas);
    cudaGetSymbolAddress((void**)&WH, g_WH);
    cudaGetSymbolAddress((void**)&WL, g_WL);

    int ebE = (E + 255) / 256;

    // CSR build
    fill_zero_kernel<<<(M / 4 + 255) / 256, 256>>>((float*)deg, M / 4);
    hist_kernel<<<ebE, 256>>>(ei, E, deg);
    scan_kernel<<<1, 1024>>>(deg, rp, M);
    copy_int_kernel<<<(M + 255) / 256, 256>>>(cursor, rp, M);
    scatter_kernel<<<ebE, 256>>>(ei, ea, cursor, esrc, eas, E);

    // weight pre-split: [W1g | W2g | W1f | W2f]
    int wsz = NLAYER * 128 * 256;  // 131072
    split_w_kernel<<<(wsz + 255) / 256, 256>>>(W1g, WH, WL, wsz);
    split_w_kernel<<<(wsz + 255) / 256, 256>>>(W2g, WH + wsz, WL + wsz, wsz);
    split_w_kernel<<<(wsz + 255) / 256, 256>>>(W1f, WH + 2 * wsz, WL + 2 * wsz, wsz);
    split_w_kernel<<<(wsz + 255) / 256, 256>>>(W2f, WH + 3 * wsz, WL + 3 * wsz, wsz);

    // BN state init
    fill_zero_kernel<<<1, 64>>>(psum, HD / 4);
    fill_zero_kernel<<<1, 64>>>(psq, HD / 4);
    init_scale2_kernel<<<1, 128>>>();

    input_proj_kernel<<<(M + 15) / 16, 128>>>(x, pe, W_in, b_in, hA, M);

    float* cur = hA;  // S buffer (pre-BN2; layer0: identity scale2)
    float* nxt = hB;
    dim3 gW(2, (M + 127) / 128);  // NC=256
    dim3 gN(1, (M + 127) / 128);  // NC=128

    for (int l = 0; l < NLAYER; l++) {
        // pull aggregate (bn2 fused into gather)
        node_agg_kernel<<<2048, 256>>>(cur, rp, esrc, eas, We + l * 16 * 128, bee + l * 128,
                                       agg, M);
        // GIN MLP: t = relu(((1+eps)*bn2(S) + agg) @ W1 + b1); z = t @ W2 + b2 (+BN1 stats)
        gemm_tc<128, 256, 1, true, 0, false><<<gW, 256>>>(
            cur, agg, eps + l, WH + (size_t)l * 32768, WL + (size_t)l * 32768,
            b1g + l * 256, nullptr, nullptr, tb, M);
        gemm_tc<256, 128, 0, false, 0, true><<<gN, 256>>>(
            tb, nullptr, nullptr, WH + wsz + (size_t)l * 32768, WL + wsz + (size_t)l * 32768,
            b2g + l * 128, nullptr, nullptr, zb, M);
        bn_finalize_kernel<<<1, 128>>>(bn1g + l * 128, bn1b + l * 128, M, sc1, sh1);
        // FFN: zres = relu(bn1(z)) + bn2(S) on the fly
        gemm_tc<128, 256, 2, true, 0, false><<<gW, 256>>>(
            zb, cur, nullptr, WH + 2 * wsz + (size_t)l * 32768, WL + 2 * wsz + (size_t)l * 32768,
            b1f + l * 256, nullptr, nullptr, tb, M);
        gemm_tc<256, 128, 0, false, 2, true><<<gN, 256>>>(
            tb, nullptr, nullptr, WH + 3 * wsz + (size_t)l * 32768, WL + 3 * wsz + (size_t)l * 32768,
            b2f + l * 128, zb, cur, nxt, M);
        bn_finalize_kernel<<<1, 128>>>(bn2g + l * 128, bn2b + l * 128, M, sc2, sh2);
        float* tmp = cur; cur = nxt; nxt = tmp;
    }

    // Global mean pool (bn2 fused) + readout
    fill_zero_kernel<<<(NGRAPH * 32 + 255) / 256, 256>>>(hg, NGRAPH * 32);
    fill_zero_kernel<<<1, 64>>>(cnt, NGRAPH / 4);
    pool_kernel<<<(M + 63) / 64, 128>>>(cur, batch, M);
    pool_norm_kernel<<<(NGRAPH * HD + 255) / 256, 256>>>();
    readout_kernel<<<1, 256>>>(Wr1, br1, Wr2, br2, out);
}